// round 15
// baseline (speedup 1.0000x reference)
#include <cuda_runtime.h>

#define BB 4
#define FF 256
#define TT 256
#define DD 16
#define YY 320
#define NCH 8           // f-split chunks for t-attn pass 1
#define CHF (FF/NCH)    // 32 f per chunk
#define T_BLK 8         // t per tstats block
#define OUT_OFF (BB*64*FF*TT)

// ---------------- scratch (device globals; allocation is forbidden) ----------
__device__ float g_qf [BB*TT*FF*DD];   // [b][t][f][c]  (pre-scaled by 0.25)
__device__ float g_kf [BB*TT*FF*DD];   // [b][t][y][c]
__device__ float g_v  [BB*TT*FF*DD];   // [b][t][y][c]
__device__ float g_qt [BB*FF*TT*DD];   // [b][f][t][c]  (pre-scaled by 0.25)
__device__ float g_kt [BB*FF*YY*DD];   // [b][f][y][c]   (y<64 from k_cache)
__device__ float g_fo [BB*FF*YY*DD];   // [b][f][y][c]   (y<64 from v_cache, y>=64 f-attn out)
__device__ float g_to [BB*FF*TT*DD];   // [b][f][t][c]   t-attn output
__device__ float g_pm [BB*NCH*YY*TT];  // partial max  [b][ch][y][t]
__device__ float g_pl [BB*NCH*YY*TT];  // partial sum  [b][ch][y][t]
__device__ float g_ma [BB*YY*TT];      // m + ln(l)    [b][y][t]

// ---------------- helpers -----------------------------------------------------
__device__ __forceinline__ float dot4(float4 a, float4 b) {
    return fmaf(a.x, b.x, fmaf(a.y, b.y, fmaf(a.z, b.z, a.w * b.w)));
}
__device__ __forceinline__ float4 fma4(float4 a, float s, float4 c) {
    return make_float4(fmaf(a.x, s, c.x), fmaf(a.y, s, c.y),
                       fmaf(a.z, s, c.z), fmaf(a.w, s, c.w));
}
__device__ __forceinline__ float4 mul4(float4 a, float s) {
    return make_float4(a.x * s, a.y * s, a.z * s, a.w * s);
}

// ======================= K1: fused fqkv + tqk conv + BN + PReLU ===============
// grid (FF, BB), 256 threads (t). One pass over inp produces all 5 tensors.
// The attention scale 1/sqrt(D)=0.25 is folded into the q outputs (post-PReLU).
__global__ __launch_bounds__(256) void k_convs(
    const float* __restrict__ inp,
    const float* __restrict__ fw, const float* __restrict__ fg,
    const float* __restrict__ fb, const float* __restrict__ fm,
    const float* __restrict__ fv, const float* __restrict__ fa,
    const float* __restrict__ tw, const float* __restrict__ tg,
    const float* __restrict__ tb, const float* __restrict__ tm,
    const float* __restrict__ tv, const float* __restrict__ ta)
{
    __shared__ float4 wsf[48*16], wst[32*16];
    __shared__ float scf[48], shf[48], alf[48], sct[32], sht[32], alt[32];
    const int f = blockIdx.x, b = blockIdx.y, t = threadIdx.x;
    for (int i = t; i < 48*16; i += 256) wsf[i] = reinterpret_cast<const float4*>(fw)[i];
    for (int i = t; i < 32*16; i += 256) wst[i] = reinterpret_cast<const float4*>(tw)[i];
    if (t < 48) {
        float inv = rsqrtf(fv[t] + 1e-5f);
        scf[t] = fg[t] * inv;  shf[t] = fb[t] - fg[t] * fm[t] * inv;  alf[t] = fa[t];
    }
    if (t < 32) {
        float inv = rsqrtf(tv[t] + 1e-5f);
        sct[t] = tg[t] * inv;  sht[t] = tb[t] - tg[t] * tm[t] * inv;  alt[t] = ta[t];
    }
    __syncthreads();
    float4 x[16];
    const float* ip = inp + ((b*64)*256 + f)*256 + t;
    #pragma unroll
    for (int j = 0; j < 16; j++) {
        x[j].x = ip[(4*j+0)*65536];
        x[j].y = ip[(4*j+1)*65536];
        x[j].z = ip[(4*j+2)*65536];
        x[j].w = ip[(4*j+3)*65536];
    }
    const int base_f = (((b*256 + t)*256) + f)*16;   // [b][t][f][c]
    #pragma unroll
    for (int grp = 0; grp < 3; grp++) {
        float o16[16];
        #pragma unroll
        for (int oo = 0; oo < 16; oo++) {
            const int o = grp*16 + oo;
            float s = 0.f;
            #pragma unroll
            for (int j = 0; j < 16; j++) s += dot4(wsf[o*16 + j], x[j]);
            float y = fmaf(s, scf[o], shf[o]);
            y = (y >= 0.f) ? y : alf[o] * y;
            o16[oo] = (grp == 0) ? y * 0.25f : y;     // fold 1/sqrt(D) into qf
        }
        float* dst = (grp == 0) ? g_qf : (grp == 1) ? g_kf : g_v;
        float4* d4 = reinterpret_cast<float4*>(dst + base_f);
        #pragma unroll
        for (int j = 0; j < 4; j++)
            d4[j] = make_float4(o16[4*j], o16[4*j+1], o16[4*j+2], o16[4*j+3]);
    }
    const int base_q = (((b*256 + f)*256) + t)*16;        // [b][f][t][c]
    const int base_k = (((b*256 + f)*320) + 64 + t)*16;   // [b][f][64+t][c]
    #pragma unroll
    for (int grp = 0; grp < 2; grp++) {
        float o16[16];
        #pragma unroll
        for (int oo = 0; oo < 16; oo++) {
            const int o = grp*16 + oo;
            float s = 0.f;
            #pragma unroll
            for (int j = 0; j < 16; j++) s += dot4(wst[o*16 + j], x[j]);
            float y = fmaf(s, sct[o], sht[o]);
            y = (y >= 0.f) ? y : alt[o] * y;
            o16[oo] = (grp == 0) ? y * 0.25f : y;     // fold 1/sqrt(D) into qt
        }
        float4* d4 = reinterpret_cast<float4*>(((grp == 0) ? g_qt : g_kt) +
                                               ((grp == 0) ? base_q : base_k));
        #pragma unroll
        for (int j = 0; j < 4; j++)
            d4[j] = make_float4(o16[4*j], o16[4*j+1], o16[4*j+2], o16[4*j+3]);
    }
}

// ======================= K2: cache transpose-in ================================
__global__ __launch_bounds__(256) void k_cachein(const float* __restrict__ cache)
{
    const int f = blockIdx.x, b = blockIdx.y;
    for (int i = threadIdx.x; i < 32*64; i += 256) {
        const int ch = i >> 6, tc = i & 63;
        const float val = cache[(((b*32 + ch)*256 + f) << 6) + tc];
        if (ch < 16) g_kt[((b*256 + f)*320 + tc)*16 + ch] = val;
        else         g_fo[((b*256 + f)*320 + tc)*16 + (ch - 16)] = val;
    }
}

// ======================= K3: frequency attention (2 queries/thread) ===========
// grid (TT, BB), 128 threads. Thread handles f=tid and f=tid+128, amortizing
// the K/V shared-memory reads over 2 queries. q pre-scaled by 0.25.
__global__ __launch_bounds__(128) void k_fattn()
{
    __shared__ float4 ks[1024], vs[1024];   // 16KB + 16KB
    const int t = blockIdx.x, b = blockIdx.y, tid = threadIdx.x;
    const int base = (b*256 + t)*256*16;
    const float4* kp = reinterpret_cast<const float4*>(g_kf + base);
    const float4* vp = reinterpret_cast<const float4*>(g_v + base);
    for (int i = tid; i < 1024; i += 128) { ks[i] = kp[i]; vs[i] = vp[i]; }
    __syncthreads();

    const float4* qap = reinterpret_cast<const float4*>(g_qf + base + tid*16);
    const float4* qbp = reinterpret_cast<const float4*>(g_qf + base + (tid+128)*16);
    const float4 qa0 = qap[0], qa1 = qap[1], qa2 = qap[2], qa3 = qap[3];
    const float4 qb0 = qbp[0], qb1 = qbp[1], qb2 = qbp[2], qb3 = qbp[3];
    float4 aa0 = {0,0,0,0}, aa1 = aa0, aa2 = aa0, aa3 = aa0;
    float4 ab0 = aa0, ab1 = aa0, ab2 = aa0, ab3 = aa0;
    float mxa = -1e30f, la = 0.f, mxb = -1e30f, lb = 0.f;
    for (int y = 0; y < 256; y++) {
        const float4 k0 = ks[y*4+0], k1 = ks[y*4+1], k2 = ks[y*4+2], k3 = ks[y*4+3];
        const float4 v0 = vs[y*4+0], v1 = vs[y*4+1], v2 = vs[y*4+2], v3 = vs[y*4+3];
        const float sa = dot4(qa0,k0)+dot4(qa1,k1)+dot4(qa2,k2)+dot4(qa3,k3);
        const float sb = dot4(qb0,k0)+dot4(qb1,k1)+dot4(qb2,k2)+dot4(qb3,k3);
        if (sa <= mxa) {
            const float p = __expf(sa - mxa);
            la += p;
            aa0 = fma4(v0,p,aa0); aa1 = fma4(v1,p,aa1); aa2 = fma4(v2,p,aa2); aa3 = fma4(v3,p,aa3);
        } else {
            const float r = __expf(mxa - sa);
            la = fmaf(la, r, 1.f);
            aa0 = fma4(aa0,r,v0); aa1 = fma4(aa1,r,v1); aa2 = fma4(aa2,r,v2); aa3 = fma4(aa3,r,v3);
            mxa = sa;
        }
        if (sb <= mxb) {
            const float p = __expf(sb - mxb);
            lb += p;
            ab0 = fma4(v0,p,ab0); ab1 = fma4(v1,p,ab1); ab2 = fma4(v2,p,ab2); ab3 = fma4(v3,p,ab3);
        } else {
            const float r = __expf(mxb - sb);
            lb = fmaf(lb, r, 1.f);
            ab0 = fma4(ab0,r,v0); ab1 = fma4(ab1,r,v1); ab2 = fma4(ab2,r,v2); ab3 = fma4(ab3,r,v3);
            mxb = sb;
        }
    }
    const float rla = __fdividef(1.f, la);
    const float rlb = __fdividef(1.f, lb);
    float4* oa = reinterpret_cast<float4*>(g_fo + ((b*256 + tid)*320 + 64 + t)*16);
    oa[0] = mul4(aa0, rla); oa[1] = mul4(aa1, rla); oa[2] = mul4(aa2, rla); oa[3] = mul4(aa3, rla);
    float4* ob = reinterpret_cast<float4*>(g_fo + ((b*256 + tid + 128)*320 + 64 + t)*16);
    ob[0] = mul4(ab0, rlb); ob[1] = mul4(ab1, rlb); ob[2] = mul4(ab2, rlb); ob[3] = mul4(ab3, rlb);
}

// ======================= K4: t-attn pass 1 (barrier-free, 2 y-rows/thread) ====
// grid (TT/T_BLK, NCH, BB), 160 threads. Thread handles y=tid and y=tid+160.
// NO smem, NO barriers: q rows are read via uniform __ldg (warp broadcast,
// L1-resident); k rows stream GMEM->regs double-buffered. Warps self-pace —
// no cross-warp coupling to the slowest LDG tail.
__global__ __launch_bounds__(160) void k_tstats()
{
    const int tg = blockIdx.x, ch = blockIdx.y, b = blockIdx.z, tid = threadIdx.x;
    float mxa[T_BLK], la[T_BLK], mxb[T_BLK], lb[T_BLK];
    #pragma unroll
    for (int i = 0; i < T_BLK; i++) {
        mxa[i] = -1e30f; la[i] = 0.f;
        mxb[i] = -1e30f; lb[i] = 0.f;
    }

    const int f0 = ch * CHF;
    const float4* ka_src = reinterpret_cast<const float4*>(g_kt) +
                           ((size_t)(b*256 + f0)*YY + tid)*4;        // y = tid
    const float4* kb_src = ka_src + 160*4;                           // y = tid+160
    const float4* qsrc = reinterpret_cast<const float4*>(g_qt) +
                         ((size_t)(b*256 + f0)*256 + tg*T_BLK)*4;

    // prologue: k rows f0 -> registers
    float4 a0 = ka_src[0], a1 = ka_src[1], a2 = ka_src[2], a3 = ka_src[3];
    float4 c0 = kb_src[0], c1 = kb_src[1], c2 = kb_src[2], c3 = kb_src[3];

    for (int ff = 0; ff < CHF; ff++) {
        float4 na0, na1, na2, na3, nc0, nc1, nc2, nc3;
        if (ff + 1 < CHF) {
            const float4* ka2 = ka_src + (size_t)(ff+1)*YY*4;
            const float4* kb2 = kb_src + (size_t)(ff+1)*YY*4;
            na0 = ka2[0]; na1 = ka2[1]; na2 = ka2[2]; na3 = ka2[3];
            nc0 = kb2[0]; nc1 = kb2[1]; nc2 = kb2[2]; nc3 = kb2[3];
        }
        const float4* qf = qsrc + (size_t)ff*256*4;
        #pragma unroll
        for (int tt = 0; tt < T_BLK; tt++) {
            const float4 q0 = __ldg(qf + tt*4 + 0);
            const float4 q1 = __ldg(qf + tt*4 + 1);
            const float4 q2 = __ldg(qf + tt*4 + 2);
            const float4 q3 = __ldg(qf + tt*4 + 3);
            const float sa = dot4(q0,a0)+dot4(q1,a1)+dot4(q2,a2)+dot4(q3,a3);
            const float sb = dot4(q0,c0)+dot4(q1,c1)+dot4(q2,c2)+dot4(q3,c3);
            {   // branchless online update, single exp (row a)
                const float d  = sa - mxa[tt];
                const float e  = __expf(-fabsf(d));
                const bool  gt = d > 0.f;
                la[tt]  = fmaf(la[tt], gt ? e : 1.f, gt ? 1.f : e);
                mxa[tt] = fmaxf(mxa[tt], sa);
            }
            {   // row b
                const float d  = sb - mxb[tt];
                const float e  = __expf(-fabsf(d));
                const bool  gt = d > 0.f;
                lb[tt]  = fmaf(lb[tt], gt ? e : 1.f, gt ? 1.f : e);
                mxb[tt] = fmaxf(mxb[tt], sb);
            }
        }
        if (ff + 1 < CHF) {
            a0 = na0; a1 = na1; a2 = na2; a3 = na3;
            c0 = nc0; c1 = nc1; c2 = nc2; c3 = nc3;
        }
    }
    #pragma unroll
    for (int tt = 0; tt < T_BLK; tt++) {
        const int idx_a = (((b*NCH + ch)*YY) + tid)*256 + tg*T_BLK + tt;
        g_pm[idx_a] = mxa[tt];
        g_pl[idx_a] = la[tt];
        const int idx_b = idx_a + 160*256;
        g_pm[idx_b] = mxb[tt];
        g_pl[idx_b] = lb[tt];
    }
}

// ======================= K5: combine partials -> m_adj = m + ln(l) ============
__global__ __launch_bounds__(256) void k_tcomb()
{
    const int i = blockIdx.x * 256 + threadIdx.x;      // i in [0, BB*YY*TT)
    const int b = i / (YY*TT);
    const int yt = i - b * (YY*TT);
    const int base = (b*NCH)*(YY*TT) + yt;
    float pm[NCH], pl[NCH];
    #pragma unroll
    for (int c = 0; c < NCH; c++) {
        pm[c] = g_pm[base + c*(YY*TT)];
        pl[c] = g_pl[base + c*(YY*TT)];
    }
    float m = pm[0];
    #pragma unroll
    for (int c = 1; c < NCH; c++) m = fmaxf(m, pm[c]);
    float l = 0.f;
    #pragma unroll
    for (int c = 0; c < NCH; c++) l = fmaf(pl[c], __expf(pm[c] - m), l);
    g_ma[i] = m + __logf(l);
}

// ======================= K6: t-attn pass 2 (weighted sum over y) ==============
// grid (FF, BB), 256 threads (t). p = exp(s - m_adj); q pre-scaled by 0.25.
__global__ __launch_bounds__(256) void k_tattn()
{
    __shared__ float4 ks[128], fs[128];
    const int f = blockIdx.x, b = blockIdx.y, t = threadIdx.x;
    const size_t base = (size_t)(b*256 + f)*320*16;
    const float4* kp = reinterpret_cast<const float4*>(g_kt + base);
    const float4* fp = reinterpret_cast<const float4*>(g_fo + base);

    const float4* qp = reinterpret_cast<const float4*>(g_qt + ((size_t)(b*256 + f)*256 + t)*16);
    const float4 q0 = qp[0], q1 = qp[1], q2 = qp[2], q3 = qp[3];
    float4 a0 = {0,0,0,0}, a1 = a0, a2 = a0, a3 = a0;

    const float* map = g_ma + (size_t)(b*320)*256 + t;

    for (int yc = 0; yc < 10; yc++) {
        __syncthreads();
        if (t < 128) ks[t]       = kp[yc*128 + t];
        else         fs[t - 128] = fp[yc*128 + (t - 128)];
        __syncthreads();
        #pragma unroll 4
        for (int yy = 0; yy < 32; yy++) {
            const float4 k0 = ks[yy*4+0], k1 = ks[yy*4+1], k2 = ks[yy*4+2], k3 = ks[yy*4+3];
            const float s = dot4(q0,k0)+dot4(q1,k1)+dot4(q2,k2)+dot4(q3,k3);
            const int y = yc*32 + yy;
            const float p = __expf(s - map[(size_t)y*256]);
            const float4 f0 = fs[yy*4+0], f1 = fs[yy*4+1], f2 = fs[yy*4+2], f3 = fs[yy*4+3];
            a0 = fma4(f0,p,a0); a1 = fma4(f1,p,a1); a2 = fma4(f2,p,a2); a3 = fma4(f3,p,a3);
        }
    }
    float4* op = reinterpret_cast<float4*>(g_to + ((size_t)(b*256 + f)*256 + t)*16);
    op[0] = a0; op[1] = a1; op[2] = a2; op[3] = a3;
}

// ======================= K7: proj conv + BN + PReLU + residual ================
__global__ __launch_bounds__(256) void k_proj(
    const float* __restrict__ inp, const float* __restrict__ w,
    const float* __restrict__ gg, const float* __restrict__ bb,
    const float* __restrict__ mm, const float* __restrict__ vv,
    const float* __restrict__ aa, float* __restrict__ out)
{
    __shared__ float4 pw[64*4];
    __shared__ float sc[64], sh[64], al[64];
    const int f = blockIdx.x, b = blockIdx.y, t = threadIdx.x;
    if (t < 64*4) pw[t] = reinterpret_cast<const float4*>(w)[t];
    if (t < 64) {
        float inv = rsqrtf(vv[t] + 1e-5f);
        sc[t] = gg[t] * inv;
        sh[t] = bb[t] - gg[t] * mm[t] * inv;
        al[t] = aa[t];
    }
    __syncthreads();
    const float4* xp = reinterpret_cast<const float4*>(g_to + ((size_t)(b*256 + f)*256 + t)*16);
    const float4 x0 = xp[0], x1 = xp[1], x2 = xp[2], x3 = xp[3];
    const int base = ((b*64)*256 + f)*256 + t;
    #pragma unroll 8
    for (int o = 0; o < 64; o++) {
        const float s = dot4(pw[o*4+0],x0)+dot4(pw[o*4+1],x1)+dot4(pw[o*4+2],x2)+dot4(pw[o*4+3],x3);
        float y = fmaf(s, sc[o], sh[o]);
        y = (y >= 0.f) ? y : al[o] * y;
        out[base + o*65536] = y + inp[base + o*65536];
    }
}

// ======================= K8: new_cache transpose-out ==========================
__global__ __launch_bounds__(256) void k_cacheout(float* __restrict__ out)
{
    __shared__ float sk[320*17], sv[320*17];
    const int f = blockIdx.x, b = blockIdx.y, tid = threadIdx.x;
    const float4* kp = reinterpret_cast<const float4*>(g_kt + (size_t)(b*256 + f)*320*16);
    const float4* vp = reinterpret_cast<const float4*>(g_fo + (size_t)(b*256 + f)*320*16);
    for (int i = tid; i < 1280; i += 256) {
        const int yy = i >> 2, j = i & 3;
        const float4 kv = kp[i], vv4 = vp[i];
        sk[yy*17 + j*4 + 0] = kv.x;  sk[yy*17 + j*4 + 1] = kv.y;
        sk[yy*17 + j*4 + 2] = kv.z;  sk[yy*17 + j*4 + 3] = kv.w;
        sv[yy*17 + j*4 + 0] = vv4.x; sv[yy*17 + j*4 + 1] = vv4.y;
        sv[yy*17 + j*4 + 2] = vv4.z; sv[yy*17 + j*4 + 3] = vv4.w;
    }
    __syncthreads();
    float* dst = out + OUT_OFF;
    for (int i = tid; i < 32*319; i += 256) {
        const int ch = i / 319, yt = i - ch*319;
        const float val = (ch < 16) ? sk[(yt+1)*17 + ch] : sv[(yt+1)*17 + (ch-16)];
        dst[((size_t)(b*32 + ch)*256 + f)*319 + yt] = val;
    }
}

// ======================= launch ================================================
extern "C" void kernel_launch(void* const* d_in, const int* in_sizes, int n_in,
                              void* d_out, int out_size)
{
    const float* inp    = (const float*)d_in[0];
    const float* cache  = (const float*)d_in[1];
    const float* fqkv_w = (const float*)d_in[2];
    const float* fqkv_g = (const float*)d_in[3];
    const float* fqkv_b = (const float*)d_in[4];
    const float* fqkv_m = (const float*)d_in[5];
    const float* fqkv_v = (const float*)d_in[6];
    const float* fqkv_a = (const float*)d_in[7];
    const float* tqk_w  = (const float*)d_in[8];
    const float* tqk_g  = (const float*)d_in[9];
    const float* tqk_b  = (const float*)d_in[10];
    const float* tqk_m  = (const float*)d_in[11];
    const float* tqk_v  = (const float*)d_in[12];
    const float* tqk_a  = (const float*)d_in[13];
    const float* proj_w = (const float*)d_in[14];
    const float* proj_g = (const float*)d_in[15];
    const float* proj_b = (const float*)d_in[16];
    const float* proj_m = (const float*)d_in[17];
    const float* proj_v = (const float*)d_in[18];
    const float* proj_a = (const float*)d_in[19];
    float* out = (float*)d_out;

    const dim3 gBF(FF, BB);
    k_convs  <<<gBF, 256>>>(inp, fqkv_w, fqkv_g, fqkv_b, fqkv_m, fqkv_v, fqkv_a,
                            tqk_w, tqk_g, tqk_b, tqk_m, tqk_v, tqk_a);
    k_cachein<<<gBF, 256>>>(cache);
    k_fattn  <<<dim3(TT, BB), 128>>>();
    k_tstats <<<dim3(TT/T_BLK, NCH, BB), 160>>>();
    k_tcomb  <<<(BB*YY*TT)/256, 256>>>();
    k_cacheout<<<gBF, 256>>>(out);
    k_tattn  <<<gBF, 256>>>();
    k_proj   <<<gBF, 256>>>(inp, proj_w, proj_g, proj_b, proj_m, proj_v, proj_a, out);
}

// round 16
// speedup vs baseline: 1.2682x; 1.2682x over previous
#include <cuda_runtime.h>

#define BB 4
#define FF 256
#define TT 256
#define DD 16
#define YY 320
#define NCH 8           // f-split chunks for t-attn pass 1
#define CHF (FF/NCH)    // 32 f per chunk
#define T_BLK 8         // t per tstats block
#define OUT_OFF (BB*64*FF*TT)

// ---------------- scratch (device globals; allocation is forbidden) ----------
__device__ float g_qf [BB*TT*FF*DD];   // [b][t][f][c]  (pre-scaled by 0.25)
__device__ float g_kf [BB*TT*FF*DD];   // [b][t][y][c]
__device__ float g_v  [BB*TT*FF*DD];   // [b][t][y][c]
__device__ float g_qt [BB*FF*TT*DD];   // [b][f][t][c]  (pre-scaled by 0.25)
__device__ float g_kt [BB*FF*YY*DD];   // [b][f][y][c]   (y<64 from k_cache)
__device__ float g_fo [BB*FF*YY*DD];   // [b][f][y][c]   (y<64 from v_cache, y>=64 f-attn out)
__device__ float g_to [BB*FF*TT*DD];   // [b][f][t][c]   t-attn output
__device__ float g_pm [BB*NCH*YY*TT];  // partial max  [b][ch][y][t]
__device__ float g_pl [BB*NCH*YY*TT];  // partial sum  [b][ch][y][t]
__device__ float g_ma [BB*YY*TT];      // m + ln(l)    [b][y][t]

// ---------------- helpers -----------------------------------------------------
__device__ __forceinline__ float dot4(float4 a, float4 b) {
    return fmaf(a.x, b.x, fmaf(a.y, b.y, fmaf(a.z, b.z, a.w * b.w)));
}
__device__ __forceinline__ float4 fma4(float4 a, float s, float4 c) {
    return make_float4(fmaf(a.x, s, c.x), fmaf(a.y, s, c.y),
                       fmaf(a.z, s, c.z), fmaf(a.w, s, c.w));
}
__device__ __forceinline__ float4 mul4(float4 a, float s) {
    return make_float4(a.x * s, a.y * s, a.z * s, a.w * s);
}

// ======================= K1: fused fqkv + tqk conv + BN + PReLU ===============
// grid (FF, BB), 256 threads (t). One pass over inp produces all 5 tensors.
// The attention scale 1/sqrt(D)=0.25 is folded into the q outputs (post-PReLU).
__global__ __launch_bounds__(256) void k_convs(
    const float* __restrict__ inp,
    const float* __restrict__ fw, const float* __restrict__ fg,
    const float* __restrict__ fb, const float* __restrict__ fm,
    const float* __restrict__ fv, const float* __restrict__ fa,
    const float* __restrict__ tw, const float* __restrict__ tg,
    const float* __restrict__ tb, const float* __restrict__ tm,
    const float* __restrict__ tv, const float* __restrict__ ta)
{
    __shared__ float4 wsf[48*16], wst[32*16];
    __shared__ float scf[48], shf[48], alf[48], sct[32], sht[32], alt[32];
    const int f = blockIdx.x, b = blockIdx.y, t = threadIdx.x;
    for (int i = t; i < 48*16; i += 256) wsf[i] = reinterpret_cast<const float4*>(fw)[i];
    for (int i = t; i < 32*16; i += 256) wst[i] = reinterpret_cast<const float4*>(tw)[i];
    if (t < 48) {
        float inv = rsqrtf(fv[t] + 1e-5f);
        scf[t] = fg[t] * inv;  shf[t] = fb[t] - fg[t] * fm[t] * inv;  alf[t] = fa[t];
    }
    if (t < 32) {
        float inv = rsqrtf(tv[t] + 1e-5f);
        sct[t] = tg[t] * inv;  sht[t] = tb[t] - tg[t] * tm[t] * inv;  alt[t] = ta[t];
    }
    __syncthreads();
    float4 x[16];
    const float* ip = inp + ((b*64)*256 + f)*256 + t;
    #pragma unroll
    for (int j = 0; j < 16; j++) {
        x[j].x = ip[(4*j+0)*65536];
        x[j].y = ip[(4*j+1)*65536];
        x[j].z = ip[(4*j+2)*65536];
        x[j].w = ip[(4*j+3)*65536];
    }
    const int base_f = (((b*256 + t)*256) + f)*16;   // [b][t][f][c]
    #pragma unroll
    for (int grp = 0; grp < 3; grp++) {
        float o16[16];
        #pragma unroll
        for (int oo = 0; oo < 16; oo++) {
            const int o = grp*16 + oo;
            float s = 0.f;
            #pragma unroll
            for (int j = 0; j < 16; j++) s += dot4(wsf[o*16 + j], x[j]);
            float y = fmaf(s, scf[o], shf[o]);
            y = (y >= 0.f) ? y : alf[o] * y;
            o16[oo] = (grp == 0) ? y * 0.25f : y;     // fold 1/sqrt(D) into qf
        }
        float* dst = (grp == 0) ? g_qf : (grp == 1) ? g_kf : g_v;
        float4* d4 = reinterpret_cast<float4*>(dst + base_f);
        #pragma unroll
        for (int j = 0; j < 4; j++)
            d4[j] = make_float4(o16[4*j], o16[4*j+1], o16[4*j+2], o16[4*j+3]);
    }
    const int base_q = (((b*256 + f)*256) + t)*16;        // [b][f][t][c]
    const int base_k = (((b*256 + f)*320) + 64 + t)*16;   // [b][f][64+t][c]
    #pragma unroll
    for (int grp = 0; grp < 2; grp++) {
        float o16[16];
        #pragma unroll
        for (int oo = 0; oo < 16; oo++) {
            const int o = grp*16 + oo;
            float s = 0.f;
            #pragma unroll
            for (int j = 0; j < 16; j++) s += dot4(wst[o*16 + j], x[j]);
            float y = fmaf(s, sct[o], sht[o]);
            y = (y >= 0.f) ? y : alt[o] * y;
            o16[oo] = (grp == 0) ? y * 0.25f : y;     // fold 1/sqrt(D) into qt
        }
        float4* d4 = reinterpret_cast<float4*>(((grp == 0) ? g_qt : g_kt) +
                                               ((grp == 0) ? base_q : base_k));
        #pragma unroll
        for (int j = 0; j < 4; j++)
            d4[j] = make_float4(o16[4*j], o16[4*j+1], o16[4*j+2], o16[4*j+3]);
    }
}

// ======================= K2: cache transpose-in ================================
__global__ __launch_bounds__(256) void k_cachein(const float* __restrict__ cache)
{
    const int f = blockIdx.x, b = blockIdx.y;
    for (int i = threadIdx.x; i < 32*64; i += 256) {
        const int ch = i >> 6, tc = i & 63;
        const float val = cache[(((b*32 + ch)*256 + f) << 6) + tc];
        if (ch < 16) g_kt[((b*256 + f)*320 + tc)*16 + ch] = val;
        else         g_fo[((b*256 + f)*320 + tc)*16 + (ch - 16)] = val;
    }
}

// ======================= K3: frequency attention (2 queries/thread) ===========
// grid (TT, BB), 128 threads. Thread handles f=tid and f=tid+128, amortizing
// the K/V shared-memory reads over 2 queries. q pre-scaled by 0.25.
__global__ __launch_bounds__(128) void k_fattn()
{
    __shared__ float4 ks[1024], vs[1024];   // 16KB + 16KB
    const int t = blockIdx.x, b = blockIdx.y, tid = threadIdx.x;
    const int base = (b*256 + t)*256*16;
    const float4* kp = reinterpret_cast<const float4*>(g_kf + base);
    const float4* vp = reinterpret_cast<const float4*>(g_v + base);
    for (int i = tid; i < 1024; i += 128) { ks[i] = kp[i]; vs[i] = vp[i]; }
    __syncthreads();

    const float4* qap = reinterpret_cast<const float4*>(g_qf + base + tid*16);
    const float4* qbp = reinterpret_cast<const float4*>(g_qf + base + (tid+128)*16);
    const float4 qa0 = qap[0], qa1 = qap[1], qa2 = qap[2], qa3 = qap[3];
    const float4 qb0 = qbp[0], qb1 = qbp[1], qb2 = qbp[2], qb3 = qbp[3];
    float4 aa0 = {0,0,0,0}, aa1 = aa0, aa2 = aa0, aa3 = aa0;
    float4 ab0 = aa0, ab1 = aa0, ab2 = aa0, ab3 = aa0;
    float mxa = -1e30f, la = 0.f, mxb = -1e30f, lb = 0.f;
    for (int y = 0; y < 256; y++) {
        const float4 k0 = ks[y*4+0], k1 = ks[y*4+1], k2 = ks[y*4+2], k3 = ks[y*4+3];
        const float4 v0 = vs[y*4+0], v1 = vs[y*4+1], v2 = vs[y*4+2], v3 = vs[y*4+3];
        const float sa = dot4(qa0,k0)+dot4(qa1,k1)+dot4(qa2,k2)+dot4(qa3,k3);
        const float sb = dot4(qb0,k0)+dot4(qb1,k1)+dot4(qb2,k2)+dot4(qb3,k3);
        if (sa <= mxa) {
            const float p = __expf(sa - mxa);
            la += p;
            aa0 = fma4(v0,p,aa0); aa1 = fma4(v1,p,aa1); aa2 = fma4(v2,p,aa2); aa3 = fma4(v3,p,aa3);
        } else {
            const float r = __expf(mxa - sa);
            la = fmaf(la, r, 1.f);
            aa0 = fma4(aa0,r,v0); aa1 = fma4(aa1,r,v1); aa2 = fma4(aa2,r,v2); aa3 = fma4(aa3,r,v3);
            mxa = sa;
        }
        if (sb <= mxb) {
            const float p = __expf(sb - mxb);
            lb += p;
            ab0 = fma4(v0,p,ab0); ab1 = fma4(v1,p,ab1); ab2 = fma4(v2,p,ab2); ab3 = fma4(v3,p,ab3);
        } else {
            const float r = __expf(mxb - sb);
            lb = fmaf(lb, r, 1.f);
            ab0 = fma4(ab0,r,v0); ab1 = fma4(ab1,r,v1); ab2 = fma4(ab2,r,v2); ab3 = fma4(ab3,r,v3);
            mxb = sb;
        }
    }
    const float rla = __fdividef(1.f, la);
    const float rlb = __fdividef(1.f, lb);
    float4* oa = reinterpret_cast<float4*>(g_fo + ((b*256 + tid)*320 + 64 + t)*16);
    oa[0] = mul4(aa0, rla); oa[1] = mul4(aa1, rla); oa[2] = mul4(aa2, rla); oa[3] = mul4(aa3, rla);
    float4* ob = reinterpret_cast<float4*>(g_fo + ((b*256 + tid + 128)*320 + 64 + t)*16);
    ob[0] = mul4(ab0, rlb); ob[1] = mul4(ab1, rlb); ob[2] = mul4(ab2, rlb); ob[3] = mul4(ab3, rlb);
}

// ======================= K4: t-attn pass 1 (whole q-chunk in smem) ============
// grid (TT/T_BLK, NCH, BB), 160 threads. Thread handles y=tid and y=tid+160.
// The ENTIRE q chunk (CHF=32 f x T_BLK=8 t x 16 c = 16KB) is staged in smem
// ONCE (single barrier per kernel). The per-f loop is barrier-free: k rows
// stream GMEM->regs (double-buffered, self-paced per warp), q comes from
// 1-phase LDS.128 broadcasts.
__global__ __launch_bounds__(160) void k_tstats()
{
    __shared__ float4 qs[CHF*T_BLK*4];     // 1024 float4 = 16KB
    const int tg = blockIdx.x, ch = blockIdx.y, b = blockIdx.z, tid = threadIdx.x;
    float mxa[T_BLK], la[T_BLK], mxb[T_BLK], lb[T_BLK];
    #pragma unroll
    for (int i = 0; i < T_BLK; i++) {
        mxa[i] = -1e30f; la[i] = 0.f;
        mxb[i] = -1e30f; lb[i] = 0.f;
    }

    const int f0 = ch * CHF;
    const float4* ka_src = reinterpret_cast<const float4*>(g_kt) +
                           ((size_t)(b*256 + f0)*YY + tid)*4;        // y = tid
    const float4* kb_src = ka_src + 160*4;                           // y = tid+160
    const float4* qsrc = reinterpret_cast<const float4*>(g_qt) +
                         ((size_t)(b*256 + f0)*256 + tg*T_BLK)*4;

    // stage whole q chunk: qs[ff*32 + j] = q row data for (f0+ff, t=tg*8 + j/4)
    for (int i = tid; i < CHF*T_BLK*4; i += 160) {
        const int ff = i >> 5;          // /32  (T_BLK*4 = 32 float4 per f)
        const int j  = i & 31;
        qs[i] = qsrc[(size_t)ff*256*4 + j];
    }
    // prologue: k rows f0 -> registers (overlaps the q staging LDGs)
    float4 a0 = ka_src[0], a1 = ka_src[1], a2 = ka_src[2], a3 = ka_src[3];
    float4 c0 = kb_src[0], c1 = kb_src[1], c2 = kb_src[2], c3 = kb_src[3];
    __syncthreads();                    // the ONLY barrier in this kernel

    for (int ff = 0; ff < CHF; ff++) {
        float4 na0, na1, na2, na3, nc0, nc1, nc2, nc3;
        if (ff + 1 < CHF) {
            const float4* ka2 = ka_src + (size_t)(ff+1)*YY*4;
            const float4* kb2 = kb_src + (size_t)(ff+1)*YY*4;
            na0 = ka2[0]; na1 = ka2[1]; na2 = ka2[2]; na3 = ka2[3];
            nc0 = kb2[0]; nc1 = kb2[1]; nc2 = kb2[2]; nc3 = kb2[3];
        }
        const float4* qf = &qs[ff*32];
        #pragma unroll
        for (int tt = 0; tt < T_BLK; tt++) {
            const float4 q0 = qf[tt*4+0], q1 = qf[tt*4+1];
            const float4 q2 = qf[tt*4+2], q3 = qf[tt*4+3];
            const float sa = dot4(q0,a0)+dot4(q1,a1)+dot4(q2,a2)+dot4(q3,a3);
            const float sb = dot4(q0,c0)+dot4(q1,c1)+dot4(q2,c2)+dot4(q3,c3);
            {   // branchless online update, single exp (row a)
                const float d  = sa - mxa[tt];
                const float e  = __expf(-fabsf(d));
                const bool  gt = d > 0.f;
                la[tt]  = fmaf(la[tt], gt ? e : 1.f, gt ? 1.f : e);
                mxa[tt] = fmaxf(mxa[tt], sa);
            }
            {   // row b
                const float d  = sb - mxb[tt];
                const float e  = __expf(-fabsf(d));
                const bool  gt = d > 0.f;
                lb[tt]  = fmaf(lb[tt], gt ? e : 1.f, gt ? 1.f : e);
                mxb[tt] = fmaxf(mxb[tt], sb);
            }
        }
        if (ff + 1 < CHF) {
            a0 = na0; a1 = na1; a2 = na2; a3 = na3;
            c0 = nc0; c1 = nc1; c2 = nc2; c3 = nc3;
        }
    }
    #pragma unroll
    for (int tt = 0; tt < T_BLK; tt++) {
        const int idx_a = (((b*NCH + ch)*YY) + tid)*256 + tg*T_BLK + tt;
        g_pm[idx_a] = mxa[tt];
        g_pl[idx_a] = la[tt];
        const int idx_b = idx_a + 160*256;
        g_pm[idx_b] = mxb[tt];
        g_pl[idx_b] = lb[tt];
    }
}

// ======================= K5: combine partials -> m_adj = m + ln(l) ============
__global__ __launch_bounds__(256) void k_tcomb()
{
    const int i = blockIdx.x * 256 + threadIdx.x;      // i in [0, BB*YY*TT)
    const int b = i / (YY*TT);
    const int yt = i - b * (YY*TT);
    const int base = (b*NCH)*(YY*TT) + yt;
    float pm[NCH], pl[NCH];
    #pragma unroll
    for (int c = 0; c < NCH; c++) {
        pm[c] = g_pm[base + c*(YY*TT)];
        pl[c] = g_pl[base + c*(YY*TT)];
    }
    float m = pm[0];
    #pragma unroll
    for (int c = 1; c < NCH; c++) m = fmaxf(m, pm[c]);
    float l = 0.f;
    #pragma unroll
    for (int c = 0; c < NCH; c++) l = fmaf(pl[c], __expf(pm[c] - m), l);
    g_ma[i] = m + __logf(l);
}

// ======================= K6: t-attn pass 2 (weighted sum over y) ==============
// grid (FF, BB), 256 threads (t). p = exp(s - m_adj); q pre-scaled by 0.25.
__global__ __launch_bounds__(256) void k_tattn()
{
    __shared__ float4 ks[128], fs[128];
    const int f = blockIdx.x, b = blockIdx.y, t = threadIdx.x;
    const size_t base = (size_t)(b*256 + f)*320*16;
    const float4* kp = reinterpret_cast<const float4*>(g_kt + base);
    const float4* fp = reinterpret_cast<const float4*>(g_fo + base);

    const float4* qp = reinterpret_cast<const float4*>(g_qt + ((size_t)(b*256 + f)*256 + t)*16);
    const float4 q0 = qp[0], q1 = qp[1], q2 = qp[2], q3 = qp[3];
    float4 a0 = {0,0,0,0}, a1 = a0, a2 = a0, a3 = a0;

    const float* map = g_ma + (size_t)(b*320)*256 + t;

    for (int yc = 0; yc < 10; yc++) {
        __syncthreads();
        if (t < 128) ks[t]       = kp[yc*128 + t];
        else         fs[t - 128] = fp[yc*128 + (t - 128)];
        __syncthreads();
        #pragma unroll 4
        for (int yy = 0; yy < 32; yy++) {
            const float4 k0 = ks[yy*4+0], k1 = ks[yy*4+1], k2 = ks[yy*4+2], k3 = ks[yy*4+3];
            const float s = dot4(q0,k0)+dot4(q1,k1)+dot4(q2,k2)+dot4(q3,k3);
            const int y = yc*32 + yy;
            const float p = __expf(s - map[(size_t)y*256]);
            const float4 f0 = fs[yy*4+0], f1 = fs[yy*4+1], f2 = fs[yy*4+2], f3 = fs[yy*4+3];
            a0 = fma4(f0,p,a0); a1 = fma4(f1,p,a1); a2 = fma4(f2,p,a2); a3 = fma4(f3,p,a3);
        }
    }
    float4* op = reinterpret_cast<float4*>(g_to + ((size_t)(b*256 + f)*256 + t)*16);
    op[0] = a0; op[1] = a1; op[2] = a2; op[3] = a3;
}

// ======================= K7: proj conv + BN + PReLU + residual ================
__global__ __launch_bounds__(256) void k_proj(
    const float* __restrict__ inp, const float* __restrict__ w,
    const float* __restrict__ gg, const float* __restrict__ bb,
    const float* __restrict__ mm, const float* __restrict__ vv,
    const float* __restrict__ aa, float* __restrict__ out)
{
    __shared__ float4 pw[64*4];
    __shared__ float sc[64], sh[64], al[64];
    const int f = blockIdx.x, b = blockIdx.y, t = threadIdx.x;
    if (t < 64*4) pw[t] = reinterpret_cast<const float4*>(w)[t];
    if (t < 64) {
        float inv = rsqrtf(vv[t] + 1e-5f);
        sc[t] = gg[t] * inv;
        sh[t] = bb[t] - gg[t] * mm[t] * inv;
        al[t] = aa[t];
    }
    __syncthreads();
    const float4* xp = reinterpret_cast<const float4*>(g_to + ((size_t)(b*256 + f)*256 + t)*16);
    const float4 x0 = xp[0], x1 = xp[1], x2 = xp[2], x3 = xp[3];
    const int base = ((b*64)*256 + f)*256 + t;
    #pragma unroll 8
    for (int o = 0; o < 64; o++) {
        const float s = dot4(pw[o*4+0],x0)+dot4(pw[o*4+1],x1)+dot4(pw[o*4+2],x2)+dot4(pw[o*4+3],x3);
        float y = fmaf(s, sc[o], sh[o]);
        y = (y >= 0.f) ? y : al[o] * y;
        out[base + o*65536] = y + inp[base + o*65536];
    }
}

// ======================= K8: new_cache transpose-out ==========================
__global__ __launch_bounds__(256) void k_cacheout(float* __restrict__ out)
{
    __shared__ float sk[320*17], sv[320*17];
    const int f = blockIdx.x, b = blockIdx.y, tid = threadIdx.x;
    const float4* kp = reinterpret_cast<const float4*>(g_kt + (size_t)(b*256 + f)*320*16);
    const float4* vp = reinterpret_cast<const float4*>(g_fo + (size_t)(b*256 + f)*320*16);
    for (int i = tid; i < 1280; i += 256) {
        const int yy = i >> 2, j = i & 3;
        const float4 kv = kp[i], vv4 = vp[i];
        sk[yy*17 + j*4 + 0] = kv.x;  sk[yy*17 + j*4 + 1] = kv.y;
        sk[yy*17 + j*4 + 2] = kv.z;  sk[yy*17 + j*4 + 3] = kv.w;
        sv[yy*17 + j*4 + 0] = vv4.x; sv[yy*17 + j*4 + 1] = vv4.y;
        sv[yy*17 + j*4 + 2] = vv4.z; sv[yy*17 + j*4 + 3] = vv4.w;
    }
    __syncthreads();
    float* dst = out + OUT_OFF;
    for (int i = tid; i < 32*319; i += 256) {
        const int ch = i / 319, yt = i - ch*319;
        const float val = (ch < 16) ? sk[(yt+1)*17 + ch] : sv[(yt+1)*17 + (ch-16)];
        dst[((size_t)(b*32 + ch)*256 + f)*319 + yt] = val;
    }
}

// ======================= launch ================================================
extern "C" void kernel_launch(void* const* d_in, const int* in_sizes, int n_in,
                              void* d_out, int out_size)
{
    const float* inp    = (const float*)d_in[0];
    const float* cache  = (const float*)d_in[1];
    const float* fqkv_w = (const float*)d_in[2];
    const float* fqkv_g = (const float*)d_in[3];
    const float* fqkv_b = (const float*)d_in[4];
    const float* fqkv_m = (const float*)d_in[5];
    const float* fqkv_v = (const float*)d_in[6];
    const float* fqkv_a = (const float*)d_in[7];
    const float* tqk_w  = (const float*)d_in[8];
    const float* tqk_g  = (const float*)d_in[9];
    const float* tqk_b  = (const float*)d_in[10];
    const float* tqk_m  = (const float*)d_in[11];
    const float* tqk_v  = (const float*)d_in[12];
    const float* tqk_a  = (const float*)d_in[13];
    const float* proj_w = (const float*)d_in[14];
    const float* proj_g = (const float*)d_in[15];
    const float* proj_b = (const float*)d_in[16];
    const float* proj_m = (const float*)d_in[17];
    const float* proj_v = (const float*)d_in[18];
    const float* proj_a = (const float*)d_in[19];
    float* out = (float*)d_out;

    const dim3 gBF(FF, BB);
    k_convs  <<<gBF, 256>>>(inp, fqkv_w, fqkv_g, fqkv_b, fqkv_m, fqkv_v, fqkv_a,
                            tqk_w, tqk_g, tqk_b, tqk_m, tqk_v, tqk_a);
    k_cachein<<<gBF, 256>>>(cache);
    k_fattn  <<<dim3(TT, BB), 128>>>();
    k_tstats <<<dim3(TT/T_BLK, NCH, BB), 160>>>();
    k_tcomb  <<<(BB*YY*TT)/256, 256>>>();
    k_cacheout<<<gBF, 256>>>(out);
    k_tattn  <<<gBF, 256>>>();
    k_proj   <<<gBF, 256>>>(inp, proj_w, proj_g, proj_b, proj_m, proj_v, proj_a, out);
}